// round 5
// baseline (speedup 1.0000x reference)
#include <cuda_runtime.h>

#define EPS 1e-5f
#define NB 512
#define NF 300
#define NP 361      // 19*19 positions
#define WP 20       // row stride in floats (80B, 16B-aligned)

typedef unsigned long long ull;

// ---------------- static device scratch (no allocation allowed) ----------------
__device__ float g_Wcomb[288 * 256];        // layer-1 combined: 256 NDI + 16 (-wr) + 16 (+wc)
__device__ float g_w2t[256 * 128];          // w2 transposed [c][o]
__device__ float g_w3t[128 * 64];           // w3 transposed [c][o]
__device__ float g_w4t[64 * 4];             // w4 transposed [c][o]
__device__ float g_gbuf[(size_t)NB * NP * 128];
__device__ float g_mbuf[NB * NP * 4];

// ---------------- f32x2 packed helpers ----------------
__device__ __forceinline__ void ffma2(ull& d, ull a, ull b) {
    asm("fma.rn.f32x2 %0, %1, %2, %0;" : "+l"(d) : "l"(a), "l"(b));
}
__device__ __forceinline__ ull dup2(float v) {
    ull r; asm("mov.b64 %0, {%1, %1};" : "=l"(r) : "f"(v)); return r;
}
__device__ __forceinline__ void unpack2(ull p, float& lo, float& hi) {
    asm("mov.b64 {%0, %1}, %2;" : "=f"(lo), "=f"(hi) : "l"(p));
}
__device__ __forceinline__ float leaky(float v) { return v >= 0.f ? v : 0.01f * v; }
__device__ __forceinline__ float relu(float v)  { return v > 0.f ? v : 0.f; }

// Load 5 packed pairs = 10 consecutive floats at row + (WX?10:0). WP=20 rows are 16B aligned.
template<int WX>
__device__ __forceinline__ void load5(const float* row, ull& p0, ull& p1, ull& p2, ull& p3, ull& p4) {
    if (WX == 0) {
        ulonglong2 A = *(const ulonglong2*)(row);      // 0..3   (16B @ 0)
        ulonglong2 B = *(const ulonglong2*)(row + 4);  // 4..7   (16B @ 16)
        ull        C = *(const ull*)(row + 8);         // 8..9   (8B  @ 32)
        p0 = A.x; p1 = A.y; p2 = B.x; p3 = B.y; p4 = C;
    } else {
        ull        A = *(const ull*)(row);             // 10..11 (8B  @ 40)
        ulonglong2 B = *(const ulonglong2*)(row + 2);  // 12..15 (16B @ 48)
        ulonglong2 C = *(const ulonglong2*)(row + 6);  // 16..19 (16B @ 64)
        p0 = A; p1 = B.x; p2 = B.y; p3 = C.x; p4 = C.y;
    }
}

// ---------------- per-chunk compute bodies ----------------
// layer-1 chunk: 32 k-rows, 2 outputs x 10 w
template<int WX>
__device__ __forceinline__ void l1_chunk(ull a0[5], ull a1[5], const float* nb, const float* wb) {
    #pragma unroll 4
    for (int r = 0; r < 32; ++r) {
        ull p0, p1, p2, p3, p4;
        load5<WX>(nb + r * WP, p0, p1, p2, p3, p4);
        float2 wv = *(const float2*)(wb + r * 256);
        ull d0 = dup2(wv.x), d1 = dup2(wv.y);
        ffma2(a0[0], p0, d0); ffma2(a0[1], p1, d0); ffma2(a0[2], p2, d0); ffma2(a0[3], p3, d0); ffma2(a0[4], p4, d0);
        ffma2(a1[0], p0, d1); ffma2(a1[1], p1, d1); ffma2(a1[2], p2, d1); ffma2(a1[3], p3, d1); ffma2(a1[4], p4, d1);
    }
}
// layer-2 chunk: 64 k-rows, 1 output x 10 w
template<int WX>
__device__ __forceinline__ void l2_chunk(ull a[5], const float* nb, const float* wb) {
    #pragma unroll 4
    for (int r = 0; r < 64; ++r) {
        ull p0, p1, p2, p3, p4;
        load5<WX>(nb + r * WP, p0, p1, p2, p3, p4);
        ull d0 = dup2(wb[r * 128]);
        ffma2(a[0], p0, d0); ffma2(a[1], p1, d0); ffma2(a[2], p2, d0); ffma2(a[3], p3, d0); ffma2(a[4], p4, d0);
    }
}
// layer-3: 128 k-rows, 1 output x 10 w
template<int WX>
__device__ __forceinline__ void l3_all(ull a[5], const float* nb, const float* wb) {
    #pragma unroll 4
    for (int k = 0; k < 128; ++k) {
        ull p0, p1, p2, p3, p4;
        load5<WX>(nb + k * WP, p0, p1, p2, p3, p4);
        ull d0 = dup2(wb[k * 64]);
        ffma2(a[0], p0, d0); ffma2(a[1], p1, d0); ffma2(a[2], p2, d0); ffma2(a[3], p3, d0); ffma2(a[4], p4, d0);
    }
}

// ---------------- prep kernel: weight repack ----------------
__global__ void prep_kernel(const float* __restrict__ w1, const float* __restrict__ w2,
                            const float* __restrict__ w3, const float* __restrict__ w4) {
    int idx = blockIdx.x * blockDim.x + threadIdx.x;
    int stride = gridDim.x * blockDim.x;
    for (int t = idx; t < 288 * 256; t += stride) {
        int k = t >> 8, o = t & 255;
        float v;
        if (k < 256) {
            int i = k >> 4, j = k & 15;
            v = w1[o * 512 + i * 32 + j * 2 + 1];
        } else if (k < 272) {
            int i = k - 256;
            float s = 0.f;
            #pragma unroll
            for (int j = 0; j < 16; j++) s += w1[o * 512 + i * 32 + j * 2];
            v = -s;
        } else {
            int j = k - 272;
            float s = 0.f;
            #pragma unroll
            for (int i = 0; i < 16; i++) s += w1[o * 512 + i * 32 + j * 2];
            v = s;
        }
        g_Wcomb[k * 256 + o] = v;
    }
    for (int t = idx; t < 256 * 128; t += stride) {
        int k = t >> 7, o = t & 127;
        g_w2t[t] = w2[o * 256 + k];
    }
    for (int t = idx; t < 128 * 64; t += stride) {
        int k = t >> 6, o = t & 63;
        g_w3t[t] = w3[o * 128 + k];
    }
    for (int t = idx; t < 256; t += stride) {
        int c = t >> 2, oh = t & 3;
        g_w4t[t] = w4[oh * 64 + c];
    }
}

// ---------------- main fused kernel: 512 threads, one block per (b, h-pair) ----------------
__global__ __launch_bounds__(512, 1) void mlp_kernel(const float* __restrict__ x,
                                                     const float* __restrict__ b1,
                                                     const float* __restrict__ b2,
                                                     const float* __restrict__ b3,
                                                     const float* __restrict__ b4) {
    extern __shared__ float sm[];
    float* s_xp = sm;                 // 320 (later reused for w4t, 256)
    float* s_N  = sm + 320;           // 2 * 288 * 20 = 11520
    float* s_h1 = s_N + 11520;        // 2 * 256 * 20 = 10240
    float* s_h2 = s_h1 + 10240;       // 2 * 128 * 20 = 5120
    float* s_wb = s_h2 + 5120;        // 2 * 8192 weight staging (double buffer)
    // s_m3 aliases s_N (dead after layer 1): 2 * 64*20

    const int b  = blockIdx.x;
    const int h0 = blockIdx.y * 2;
    const int tid = threadIdx.x;

    // ---- prefetch W1 chunk 0 early (16 floats/thread via 4 float4) ----
    float4 pf0, pf1, pf2, pf3;
    {
        const float4* src = (const float4*)g_Wcomb;
        pf0 = src[tid]; pf1 = src[tid + 512]; pf2 = src[tid + 1024]; pf3 = src[tid + 1536];
    }

    // ---- padded input row ----
    for (int i = tid; i < 320; i += 512) {
        float v = 0.f;
        if (i >= 2 && i < 302) v = x[b * NF + i - 2];
        s_xp[i] = v;
    }
    __syncthreads();

    // ---- build N for both hh ----
    for (int e = tid; e < 11520; e += 512) {
        int hh = (e >= 5760);
        int idx = e - hh * 5760;
        int k = idx / WP, w = idx - k * WP;
        int h = h0 + hh;                     // h may be 19 -> reads land in zero pad (harmless)
        float val;
        if (k < 256) {
            int i = k >> 4, j = k & 15;
            float u = s_xp[i * 19 + h];
            float v = s_xp[j * 19 + w];
            val = __fdividef(v - u, u + v + EPS);
        } else if (k < 272) {
            val = s_xp[(k - 256) * 19 + h];
        } else {
            val = s_xp[(k - 272) * 19 + w];
        }
        s_N[e] = val;
    }
    // stage W1 chunk 0 into buf0
    {
        float4* dst = (float4*)s_wb;
        dst[tid] = pf0; dst[tid + 512] = pf1; dst[tid + 1024] = pf2; dst[tid + 1536] = pf3;
    }
    __syncthreads();

    // ---- thread tiling: hh (h within pair), wx (w half), og (output group) ----
    const int hh = tid >> 8;            // 0/1
    const int t  = tid & 255;
    const int wx = t >> 7;              // 0/1 -> w0 = 0/10
    const int w0 = wx * 10;
    const int og = t & 127;
    const int hvalid = (h0 + hh) < 19;

    // ================= layer 1: 288 -> 256 (2o x 10w per thread, 512 threads) =================
    {
        const int o0 = og * 2;
        const float* myN = s_N + hh * 5760 + w0;
        ull a0[5], a1[5];
        {
            float2 bb = *(const float2*)(b1 + o0);
            ull i0 = dup2(bb.x), i1 = dup2(bb.y);
            #pragma unroll
            for (int i = 0; i < 5; i++) { a0[i] = i0; a1[i] = i1; }
        }
        for (int c = 0; c < 9; ++c) {
            // prefetch next chunk (or L2 chunk 0 on the last iter)
            float4 q0, q1, q2, q3;
            {
                const float4* s4 = (c < 8) ? (const float4*)(g_Wcomb + (c + 1) * 8192)
                                           : (const float4*)g_w2t;
                q0 = s4[tid]; q1 = s4[tid + 512]; q2 = s4[tid + 1024]; q3 = s4[tid + 1536];
            }
            const float* wb = s_wb + (c & 1) * 8192 + o0;
            const float* nb = myN + c * 32 * WP;
            if (wx == 0) l1_chunk<0>(a0, a1, nb, wb);
            else         l1_chunk<1>(a0, a1, nb, wb);
            {
                float4* dd = (float4*)(s_wb + ((c + 1) & 1) * 8192);
                dd[tid] = q0; dd[tid + 512] = q1; dd[tid + 1024] = q2; dd[tid + 1536] = q3;
            }
            __syncthreads();
        }
        // epilogue: leaky -> s_h1
        float* myH1 = s_h1 + hh * 5120 + w0;
        float* dst0 = myH1 + o0 * WP;
        float* dst1 = dst0 + WP;
        #pragma unroll
        for (int i = 0; i < 5; ++i) {
            float lo, hi;
            unpack2(a0[i], lo, hi); dst0[2 * i] = leaky(lo); dst0[2 * i + 1] = leaky(hi);
            unpack2(a1[i], lo, hi); dst1[2 * i] = leaky(lo); dst1[2 * i + 1] = leaky(hi);
        }
    }
    __syncthreads();

    // ================= layer 2: 256 -> 128 (1o x 10w per thread, 512 threads) =================
    {
        const int o0 = og;              // 128 outputs
        const float* myH1 = s_h1 + hh * 5120 + w0;
        ull acc[5];
        {
            ull i0 = dup2(b2[o0]);
            #pragma unroll
            for (int i = 0; i < 5; i++) acc[i] = i0;
        }
        // L1 loop left w2t chunk0 in buf[1]; read buf (c&1)^1, write buf (c&1)
        for (int c = 0; c < 4; ++c) {
            float4 q0, q1, q2, q3;
            bool pf = (c < 3);
            if (pf) {
                const float4* s4 = (const float4*)(g_w2t + (c + 1) * 8192);
                q0 = s4[tid]; q1 = s4[tid + 512]; q2 = s4[tid + 1024]; q3 = s4[tid + 1536];
            }
            const float* wb = s_wb + ((c & 1) ^ 1) * 8192 + o0;
            const float* nb = myH1 + c * 64 * WP;
            if (wx == 0) l2_chunk<0>(acc, nb, wb);
            else         l2_chunk<1>(acc, nb, wb);
            if (pf) {
                float4* dd = (float4*)(s_wb + (c & 1) * 8192);
                dd[tid] = q0; dd[tid + 512] = q1; dd[tid + 1024] = q2; dd[tid + 1536] = q3;
            }
            __syncthreads();
        }
        // epilogue: leaky -> s_h2 and g_gbuf
        float v[10];
        #pragma unroll
        for (int i = 0; i < 5; ++i) {
            float lo, hi;
            unpack2(acc[i], lo, hi); v[2 * i] = leaky(lo); v[2 * i + 1] = leaky(hi);
        }
        float* d0 = s_h2 + hh * 2560 + o0 * WP + w0;
        #pragma unroll
        for (int i = 0; i < 10; ++i) d0[i] = v[i];
        if (hvalid) {
            const size_t posbase = (size_t)(b * NP + (h0 + hh) * 19);
            #pragma unroll
            for (int i = 0; i < 10; ++i) {
                int w = w0 + i;
                if (w < 19) g_gbuf[(posbase + w) * 128 + o0] = v[i];
            }
        }
        // stage whole w3t (8192 floats) into buf0 + w4t (256) into s_xp
        {
            const float4* s4 = (const float4*)g_w3t;
            float4* d4 = (float4*)s_wb;
            #pragma unroll
            for (int q = 0; q < 4; ++q) d4[tid + q * 512] = s4[tid + q * 512];
            if (tid < 256) s_xp[tid] = g_w4t[tid];
        }
    }
    __syncthreads();

    // ================= layer 3: 128 -> 64 (1o x 10w, 256 threads) =================
    if (tid < 256) {
        const int hh3 = tid >> 7, t3 = tid & 127;
        const int wx3 = t3 >> 6, w30 = wx3 * 10;
        const int o0 = t3 & 63;
        const float* myH2 = s_h2 + hh3 * 2560 + w30;
        ull acc[5];
        {
            ull i0 = dup2(b3[o0]);
            #pragma unroll
            for (int i = 0; i < 5; i++) acc[i] = i0;
        }
        if (wx3 == 0) l3_all<0>(acc, myH2, s_wb + o0);
        else          l3_all<1>(acc, myH2, s_wb + o0);
        float* m3 = s_N + hh3 * 1280;   // alias: s_N dead
        float* d0 = m3 + o0 * WP + w30;
        #pragma unroll
        for (int i = 0; i < 5; ++i) {
            float lo, hi;
            unpack2(acc[i], lo, hi); d0[2 * i] = relu(lo); d0[2 * i + 1] = relu(hi);
        }
    }
    __syncthreads();

    // ================= layer 4: 64 -> 4, logits =================
    if (tid < 152) {
        const int hh4 = (tid >= 76);
        const int tt = tid - hh4 * 76;
        const int w = tt >> 2, oh = tt & 3;
        const int h = h0 + hh4;
        const float* m3 = s_N + hh4 * 1280;
        float acc = b4[oh];
        #pragma unroll 8
        for (int c = 0; c < 64; ++c) acc += m3[c * WP + w] * s_xp[c * 4 + oh];
        if (h < 19) g_mbuf[(b * NP + h * 19 + w) * 4 + oh] = relu(acc);
    }
}

// ---------------- softmax over 361 positions + weighted reduction ----------------
__global__ __launch_bounds__(128) void softmax_kernel(float* __restrict__ out) {
    __shared__ float s_m[NP * 4];
    __shared__ float s_w[NP * 4];
    __shared__ float s_mx[4];
    __shared__ float s_iz[4];
    const int b = blockIdx.x;
    const int tid = threadIdx.x;

    for (int i = tid; i < NP * 4; i += 128) s_m[i] = g_mbuf[b * NP * 4 + i];
    __syncthreads();
    if (tid < 4) {
        float mx = -1e30f;
        for (int p = 0; p < NP; p++) mx = fmaxf(mx, s_m[p * 4 + tid]);
        s_mx[tid] = mx;
    }
    __syncthreads();
    for (int i = tid; i < NP * 4; i += 128) s_w[i] = __expf(s_m[i] - s_mx[i & 3]);
    __syncthreads();
    if (tid < 4) {
        float z = 0.f;
        for (int p = 0; p < NP; p++) z += s_w[p * 4 + tid];
        s_iz[tid] = __fdividef(1.f, z);
    }
    __syncthreads();
    const int head = tid >> 5;
    const float* gp = g_gbuf + (size_t)b * NP * 128 + tid;
    float acc = 0.f;
    #pragma unroll 4
    for (int p = 0; p < NP; p++) acc += s_w[p * 4 + head] * gp[(size_t)p * 128];
    out[b * 128 + tid] = acc * s_iz[head];
}

// ---------------- launch ----------------
extern "C" void kernel_launch(void* const* d_in, const int* in_sizes, int n_in,
                              void* d_out, int out_size) {
    const float* x  = (const float*)d_in[0];
    const float* w1 = (const float*)d_in[1];
    const float* b1 = (const float*)d_in[2];
    const float* w2 = (const float*)d_in[3];
    const float* b2 = (const float*)d_in[4];
    const float* w3 = (const float*)d_in[5];
    const float* b3 = (const float*)d_in[6];
    const float* w4 = (const float*)d_in[7];
    const float* b4 = (const float*)d_in[8];
    float* out = (float*)d_out;

    const int smem_bytes = (320 + 11520 + 10240 + 5120 + 16384) * sizeof(float); // 174336
    cudaFuncSetAttribute(mlp_kernel, cudaFuncAttributeMaxDynamicSharedMemorySize, smem_bytes);

    prep_kernel<<<128, 256>>>(w1, w2, w3, w4);
    mlp_kernel<<<dim3(NB, 10), 512, smem_bytes>>>(x, b1, b2, b3, b4);
    softmax_kernel<<<NB, 128>>>(out);
}